// round 13
// baseline (speedup 1.0000x reference)
#include <cuda_runtime.h>
#include <math.h>

#define NN 256
#define NM 240
#define NB 120
#define ITERS 30
#define NBARS 32
#define PER_LAUNCH (NBARS * NB)
#define SMEM_DYN (30 * NM * 16)   // 115200 B: At tiles kb 0..29 as float4

typedef unsigned long long u64;
union F2 { u64 u; float2 f; };
#define ONES2 0x3f8000003f800000ULL

// ---------------- device scratch ----------------
__device__ float4   g_At4[60 * NM];    // [kb*240+j] = A[j][16+4kb..16+4kb+3]
__device__ float4   g_Ab4[60 * NM];    // [jb*240+k] = A[4jb+r][16+k]
__device__ float    g_S2buf[3][256];   // triple-buffered tau-grad accumulators
__device__ float    g_Lbuf[3];         // triple-buffered loss accumulator
__device__ float    g_Lp[128];         // epilogue per-block loss partials
__device__ unsigned g_barcnt;          // monotonic across graph replays

// ---------------- helpers ----------------
static __device__ __forceinline__ unsigned ld_acq(const unsigned* p) {
    unsigned v; asm volatile("ld.acquire.gpu.global.u32 %0,[%1];" : "=r"(v) : "l"(p)); return v;
}
static __device__ __forceinline__ float ldcg(const float* p) {
    float v; asm volatile("ld.global.cg.f32 %0,[%1];" : "=f"(v) : "l"(p)); return v;
}
static __device__ __forceinline__ float4 ldcg4(const float4* p) {
    float4 v;
    asm volatile("ld.global.cg.v4.f32 {%0,%1,%2,%3},[%4];"
                 : "=f"(v.x), "=f"(v.y), "=f"(v.z), "=f"(v.w) : "l"(p));
    return v;
}
static __device__ __forceinline__ void redadd(float* p, float v) {
    asm volatile("red.global.add.f32 [%0],%1;" :: "l"(p), "f"(v) : "memory");
}
static __device__ __forceinline__ float rcpa(float x) {
    float r; asm("rcp.approx.f32 %0,%1;" : "=f"(r) : "f"(x)); return r;
}
static __device__ __forceinline__ u64 fma2_(u64 a, u64 b, u64 c) {
    u64 d; asm("fma.rn.f32x2 %0,%1,%2,%3;" : "=l"(d) : "l"(a), "l"(b), "l"(c)); return d;
}
static __device__ __forceinline__ u64 mul2_(u64 a, u64 b) {
    u64 d; asm("mul.rn.f32x2 %0,%1,%2;" : "=l"(d) : "l"(a), "l"(b)); return d;
}
static __device__ __forceinline__ float sigm(float x) { return 1.0f / (1.0f + __expf(-x)); }

#define WRED(val, dst) do { float _v = (val);                             \
    _v += __shfl_down_sync(0xffffffffu, _v, 16);                          \
    _v += __shfl_down_sync(0xffffffffu, _v, 8);                           \
    _v += __shfl_down_sync(0xffffffffu, _v, 4);                           \
    _v += __shfl_down_sync(0xffffffffu, _v, 2);                           \
    _v += __shfl_down_sync(0xffffffffu, _v, 1);                           \
    if ((tx & 31) == 0) (dst)[tx >> 5] = _v; } while (0)

static __device__ __forceinline__ float sum8(const float* w, int g) {
    float s = 0.f;
    #pragma unroll
    for (int i = 0; i < 8; ++i) s += w[g * 8 + i];
    return s;
}

#define GRIDBAR() do { __syncthreads();                                   \
    if (tx == 0) { __threadfence(); atomicAdd(&g_barcnt, 1u);             \
        while (ld_acq(&g_barcnt) < bartgt) __nanosleep(32); }             \
    bartgt += NB; __syncthreads(); } while (0)

#define QUADACC(t01u, t23u, n01u, n23u, acc, bad) do {                    \
    F2 _t0; _t0.u = (t01u); F2 _t1; _t1.u = (t23u);                       \
    F2 _n0; _n0.u = (n01u); F2 _n1; _n1.u = (n23u);                       \
    float _P01 = _t0.f.x * _t0.f.y;                                       \
    float _P23 = _t1.f.x * _t1.f.y;                                       \
    float _T = _P01 * _P23;                                               \
    float _r = rcpa(_T);                                                  \
    float _m1 = fmaf(_n0.f.y, _t0.f.x, _n0.f.x * _t0.f.y);                \
    float _m3 = fmaf(_n1.f.y, _t1.f.x, _n1.f.x * _t1.f.y);                \
    float _s = fmaf(_m3, _P01, _m1 * _P23);                               \
    bool _ok = (_T != 0.f);                                               \
    acc += _ok ? _s * _r : 0.f;                                           \
    bad |= !_ok; } while (0)

// forward quarter-product over kb = 15*QQ .. 15*QQ+14 from BASE
#define FWD15(BASE, QQ) do {                                              \
    const ulonglong2* _ap = (BASE) + (15 * (QQ)) * NM + U;                \
    ulonglong2 _an = _ap[0];                                              \
    _Pragma("unroll 5")                                                   \
    for (int _c = 0; _c < 15; ++_c) {                                     \
        ulonglong2 _a = _an;                                              \
        if (_c < 14) _an = _ap[(_c + 1) * NM];                            \
        ulonglong2 _ga = GnaP2[15 * (QQ) + _c];                           \
        ulonglong2 _gb = GnbP2[15 * (QQ) + _c];                           \
        pa0 = mul2_(pa0, fma2_(_a.x, _ga.x, ONES2));                      \
        pa1 = mul2_(pa1, fma2_(_a.y, _ga.y, ONES2));                      \
        pb0 = mul2_(pb0, fma2_(_a.x, _gb.x, ONES2));                      \
        pb1 = mul2_(pb1, fma2_(_a.y, _gb.y, ONES2));                      \
    } } while (0)

// ---------------- persistent kernel ----------------
__global__ void __launch_bounds__(1024, 1) gflow(
    const float* __restrict__ A, const float* __restrict__ Gl0,
    const float* __restrict__ tau0, float* __restrict__ out)
{
    extern __shared__ ulonglong2 AtS[];   // [kb*240+j], kb 0..29 (115.2 KB)

    const int b  = blockIdx.x;
    const int tx = threadIdx.x;
    const int Q  = tx >> 8;
    const int U  = tx & 255;
    const int r0 = b, r1 = b + NB;

    __shared__ u64   GnaP[120], GnbP[120];
    __shared__ float4 DsA4[60], DsB4[60];
    __shared__ float pfA[4 * NM], pfB[4 * NM];
    __shared__ float taus[NN];
    __shared__ float msh[NN], vsh[NN];
    __shared__ float wsum[32], wsum2[32];
    __shared__ float lsh;
    float* GnaF = (float*)GnaP;
    float* GnbF = (float*)GnbP;
    const ulonglong2* At8  = (const ulonglong2*)g_At4;
    const ulonglong2* Ab8  = (const ulonglong2*)g_Ab4;
    const ulonglong2* DsA8 = (const ulonglong2*)DsA4;
    const ulonglong2* DsB8 = (const ulonglong2*)DsB4;
    const ulonglong2* GnaP2 = (const ulonglong2*)GnaP;
    const ulonglong2* GnbP2 = (const ulonglong2*)GnbP;

    unsigned bartgt = (ld_acq(&g_barcnt) / PER_LAUNCH) * PER_LAUNCH + NB;

    // ---- init: repack A to global (both layouts) + smem copy of kb<30 ----
    if (tx < 120) {
        int e = b * 120 + tx, kb = e / NM, j = e % NM;
        g_At4[e] = *(const float4*)(A + j * NN + 16 + 4 * kb);
        float4 v;
        v.x = A[(4 * kb + 0) * NN + 16 + j];
        v.y = A[(4 * kb + 1) * NN + 16 + j];
        v.z = A[(4 * kb + 2) * NN + 16 + j];
        v.w = A[(4 * kb + 3) * NN + 16 + j];
        g_Ab4[e] = v;
    }
    for (int e = tx; e < 30 * NM; e += 1024) {
        int kb = e / NM, j = e % NM;
        ((float4*)AtS)[e] = *(const float4*)(A + j * NN + 16 + 4 * kb);
    }
    if (b == 0) {
        if (tx < 768) ((float*)g_S2buf)[tx] = 0.f;
        if (tx >= 768 && tx < 771) g_Lbuf[tx - 768] = 0.f;
    }
    float gl = 0.f, mg = 0.f, vg = 0.f;
    if (Q < 2 && U < NM) gl = Gl0[(Q ? r1 : r0) * NM + U];
    if (tx < NN) { taus[tx] = tau0[tx]; msh[tx] = 0.f; vsh[tx] = 0.f; }
    GRIDBAR();  // #1

    double b1t = 1.0, b2t = 1.0;
    float bc1p = 1.f, bc2p = 1.f;
    int stop = 0;

    for (int t = 0; t < ITERS; ++t) {
        b1t *= 0.9; b2t *= 0.999;
        const float bc1c = (float)(1.0 / (1.0 - b1t));
        const float bc2c = (float)(1.0 / (1.0 - b2t));
        const int pb = (t + 2) % 3, nxt = (t + 1) % 3, cb = t % 3;
        float* Scur = g_S2buf[cb];

        // ---- fused: tau Adam (step t-1) + Gn compute + buffer zeroing ----
        if (!stop) {
            float s2v = 0.f;
            if (t > 0) {
                if (tx < 256) s2v = ldcg(&g_S2buf[pb][tx]);
                if (tx == 0) lsh = ldcg(&g_Lbuf[pb]);
            }
            if (Q < 2 && U < NM) {
                float s = sigm(gl);
                (Q ? GnbF : GnaF)[U] = -2.f * s;
            }
            if (tx == 0) {
                g_S2buf[nxt][2 * b] = 0.f;
                g_S2buf[nxt][2 * b + 1] = 0.f;
                if (b < 16) g_S2buf[nxt][240 + b] = 0.f;
                if (b == 0) g_Lbuf[nxt] = 0.f;
            }
            if (t > 0 && tx < 256) {   // apply update BEFORE stop check (while_loop order)
                float g = -(2.f / 61440.f) * s2v;
                float mm = 0.9f * msh[tx] + 0.1f * g;
                float vv = 0.999f * vsh[tx] + 0.001f * g * g;
                msh[tx] = mm; vsh[tx] = vv;
                taus[tx] -= 0.1f * (mm * bc1p) / (sqrtf(vv * bc2p) + 1e-8f);
            }
            __syncthreads();
            if (t > 0 && lsh < 1e-3f) stop = 1;
        }

        // ---- phase A ----
        if (!stop) {
            // forward: Q<2 from smem, Q>=2 from global (identical data)
            if (U < NM) {
                u64 pa0 = ONES2, pa1 = ONES2, pb0 = ONES2, pb1 = ONES2;
                if (Q < 2) FWD15(AtS, Q); else FWD15(At8, Q);
                F2 x0; x0.u = pa0; F2 x1; x1.u = pa1;
                pfA[Q * NM + U] = (x0.f.x * x0.f.y) * (x1.f.x * x1.f.y);
                x0.u = pb0; x1.u = pb1;
                pfB[Q * NM + U] = (x0.f.x * x0.f.y) * (x1.f.x * x1.f.y);
            }
            __syncthreads();

            float v = 0.f, w = 0.f;
            int nz = 0;
            if (U < NM) {
                const int j = U;
                if (Q == 0) {
                    float P = (pfA[j] * pfA[NM + j]) * (pfA[2 * NM + j] * pfA[3 * NM + j]);
                    float e = P - ((j == r0) ? -1.f : 1.f);
                    v = e * e;
                    float ds = e * P * (1.f / 480.f);
                    ((float*)DsA4)[j] = ds;
                    nz = (ds != 0.f);
                } else if (Q == 1) {
                    float P = (pfB[j] * pfB[NM + j]) * (pfB[2 * NM + j] * pfB[3 * NM + j]);
                    float e = P - ((j == r1) ? -1.f : 1.f);
                    v = e * e;
                    float ds = e * P * (1.f / 480.f);
                    ((float*)DsB4)[j] = ds;
                    nz = (ds != 0.f);
                } else if (Q == 2) {
                    float s = -0.5f * GnaF[j];
                    float d = fmaxf(taus[r0] - taus[16 + j] + 0.1f, 0.f);
                    v = s * d * d;
                    w = s * d;
                } else {
                    float s = -0.5f * GnbF[j];
                    float d = fmaxf(taus[r1] - taus[16 + j] + 0.1f, 0.f);
                    v = s * d * d;
                    w = s * d;
                }
            }
            WRED(v, wsum);
            WRED(w, wsum2);
            int anyNZ = __syncthreads_or(nz);
            if (tx == 0) {
                float la = sum8(wsum, 0), lb = sum8(wsum, 1);
                float lo = sum8(wsum, 2) + sum8(wsum, 3);
                redadd(&g_Lbuf[cb], (la + lb) * (1.f / 960.f) + lo * (1.f / 61440.f));
                redadd(&Scur[r0], -sum8(wsum2, 2));
                redadd(&Scur[r1], -sum8(wsum2, 3));
            }

            // backward only if any Ds nonzero (P underflows to 0 in fp32)
            if (anyNZ) {
                if (U < NM) {
                    const int k = U;
                    F2 gp; gp.f.x = GnaF[k]; gp.f.y = GnaF[k];
                    const u64 gna2 = gp.u;
                    gp.f.x = GnbF[k]; gp.f.y = GnbF[k];
                    const u64 gnb2 = gp.u;
                    float accA = 0.f, accB = 0.f;
                    bool bad = false;
                    const ulonglong2* abp = Ab8 + (15 * Q) * NM + k;
                    ulonglong2 an = abp[0];
                    #pragma unroll 5
                    for (int c = 0; c < 15; ++c) {
                        ulonglong2 a = an;
                        if (c < 14) an = abp[(c + 1) * NM];
                        ulonglong2 dA = DsA8[15 * Q + c];
                        ulonglong2 dB = DsB8[15 * Q + c];
                        u64 t01 = fma2_(a.x, gna2, ONES2);
                        u64 t23 = fma2_(a.y, gna2, ONES2);
                        u64 n01 = mul2_(dA.x, a.x);
                        u64 n23 = mul2_(dA.y, a.y);
                        QUADACC(t01, t23, n01, n23, accA, bad);
                        t01 = fma2_(a.x, gnb2, ONES2);
                        t23 = fma2_(a.y, gnb2, ONES2);
                        n01 = mul2_(dB.x, a.x);
                        n23 = mul2_(dB.y, a.y);
                        QUADACC(t01, t23, n01, n23, accB, bad);
                    }
                    if (bad) {
                        accA = 0.f; accB = 0.f;
                        const float gna = GnaF[k], gnb = GnbF[k];
                        for (int c = 0; c < 15; ++c) {
                            int jb = 15 * Q + c;
                            float4 a4 = g_Ab4[jb * NM + k];
                            float4 dA = DsA4[jb], dB = DsB4[jb];
                            const float* av = (const float*)&a4;
                            const float* dv = (const float*)&dA;
                            const float* ev = (const float*)&dB;
                            #pragma unroll
                            for (int e2 = 0; e2 < 4; ++e2) {
                                float tA = fmaf(av[e2], gna, 1.f);
                                float tB = fmaf(av[e2], gnb, 1.f);
                                accA += (tA != 0.f) ? __fdividef(dv[e2] * av[e2], tA) : 0.f;
                                accB += (tB != 0.f) ? __fdividef(ev[e2] * av[e2], tB) : 0.f;
                            }
                        }
                    }
                    pfA[Q * NM + k] = accA;
                    pfB[Q * NM + k] = accB;
                }
                __syncthreads();
            }

            // Adam(G), step t
            if (Q < 2 && U < NM) {
                const int k = U;
                float S = 0.f;
                if (anyNZ) {
                    const float* pf = Q ? pfB : pfA;
                    S = (pf[k] + pf[NM + k]) + (pf[2 * NM + k] + pf[3 * NM + k]);
                }
                float s = -0.5f * (Q ? GnbF : GnaF)[k];
                float d = fmaxf(taus[Q ? r1 : r0] - taus[16 + k] + 0.1f, 0.f);
                float grad = (-2.f * S + d * d * (1.f / 61440.f)) * (s * (1.f - s));
                mg = 0.9f * mg + 0.1f * grad;
                vg = 0.999f * vg + 0.001f * grad * grad;
                gl -= 0.1f * (mg * bc1c) / (sqrtf(vg * bc2c) + 1e-8f);
            }

            // S2 contributions: atomic pre-aggregation (1 KB/iter cross-block)
            if (tx < 256 && tx >= 16) {
                const int m = tx;
                float e0 = fmaxf(taus[r0] - taus[m] + 0.1f, 0.f);
                float e1 = fmaxf(taus[r1] - taus[m] + 0.1f, 0.f);
                float c = (-0.5f * GnaF[m - 16]) * e0 + (-0.5f * GnbF[m - 16]) * e1;
                redadd(&Scur[m], c);
            }
        }
        bc1p = bc1c; bc2p = bc2c;
        GRIDBAR();  // the ONLY grid barrier this iteration
    }

    // ---- final tau update (Adam step 29) ----
    if (!stop) {
        const int pb = (ITERS - 1) % 3;
        float s = (tx < 256) ? ldcg(&g_S2buf[pb][tx]) : 0.f;
        if (tx < 256) {
            float g = -(2.f / 61440.f) * s;
            float mm = 0.9f * msh[tx] + 0.1f * g;
            float vv = 0.999f * vsh[tx] + 0.001f * g * g;
            taus[tx] -= 0.1f * (mm * bc1p) / (sqrtf(vv * bc2p) + 1e-8f);
        }
    }

    // ---- epilogue: final loss at p_final ----
    if (Q < 2 && U < NM) (Q ? GnbF : GnaF)[U] = -2.f * sigm(gl);
    __syncthreads();
    if (U < NM) {
        u64 pa0 = ONES2, pa1 = ONES2, pb0 = ONES2, pb1 = ONES2;
        if (Q < 2) FWD15(AtS, Q); else FWD15(At8, Q);
        F2 x0; x0.u = pa0; F2 x1; x1.u = pa1;
        pfA[Q * NM + U] = (x0.f.x * x0.f.y) * (x1.f.x * x1.f.y);
        x0.u = pb0; x1.u = pb1;
        pfB[Q * NM + U] = (x0.f.x * x0.f.y) * (x1.f.x * x1.f.y);
    }
    __syncthreads();
    {
        float v = 0.f;
        if (U < NM) {
            const int j = U;
            if (Q == 0) {
                float P = (pfA[j] * pfA[NM + j]) * (pfA[2 * NM + j] * pfA[3 * NM + j]);
                float e = P - ((j == r0) ? -1.f : 1.f);
                v = e * e;
            } else if (Q == 1) {
                float P = (pfB[j] * pfB[NM + j]) * (pfB[2 * NM + j] * pfB[3 * NM + j]);
                float e = P - ((j == r1) ? -1.f : 1.f);
                v = e * e;
            } else if (Q == 2) {
                float d = fmaxf(taus[r0] - taus[16 + j] + 0.1f, 0.f);
                v = (-0.5f * GnaF[j]) * d * d;
            } else {
                float d = fmaxf(taus[r1] - taus[16 + j] + 0.1f, 0.f);
                v = (-0.5f * GnbF[j]) * d * d;
            }
        }
        WRED(v, wsum);
        __syncthreads();
        if (tx == 0) {
            float la = sum8(wsum, 0), lb = sum8(wsum, 1);
            float lo = sum8(wsum, 2) + sum8(wsum, 3);
            g_Lp[b] = (la + lb) * (1.f / 960.f) + lo * (1.f / 61440.f);
        }
    }
    GRIDBAR();  // #32
    if (b == 0) {
        float lv = 0.f;
        if (tx < 30) {
            float4 q = ldcg4(((const float4*)g_Lp) + tx);
            lv = (q.x + q.y) + (q.z + q.w);
        }
        if (tx < 32) {
            lv += __shfl_down_sync(0xffffffffu, lv, 16);
            lv += __shfl_down_sync(0xffffffffu, lv, 8);
            lv += __shfl_down_sync(0xffffffffu, lv, 4);
            lv += __shfl_down_sync(0xffffffffu, lv, 2);
            lv += __shfl_down_sync(0xffffffffu, lv, 1);
            if (tx == 0) out[0] = lv;
        }
    }
}

// ---------------- launch ----------------
extern "C" void kernel_launch(void* const* d_in, const int* in_sizes, int n_in,
                              void* d_out, int out_size) {
    const float* A    = (const float*)d_in[0];
    const float* Gl0  = (const float*)d_in[1];
    const float* tau0 = (const float*)d_in[2];
    cudaFuncSetAttribute(gflow, cudaFuncAttributeMaxDynamicSharedMemorySize, SMEM_DYN);
    gflow<<<NB, 1024, SMEM_DYN>>>(A, Gl0, tau0, (float*)d_out);
}

// round 14
// speedup vs baseline: 1.2615x; 1.2615x over previous
#include <cuda_runtime.h>
#include <math.h>

#define NN 256
#define NM 240
#define NB 120
#define ITERS 30
#define NBARS 2
#define PER_LAUNCH (NBARS * NB)

typedef unsigned long long u64;
union F2 { u64 u; float2 f; };
#define ONES2 0x3f8000003f800000ULL

// ---------------- device scratch ----------------
__device__ float4   g_At4[60 * NM];    // [kb*240+j] = A[j][16+4kb..16+4kb+3]
__device__ float4   g_Ab4[60 * NM];    // [jb*240+k] = A[4jb+r][16+k]
__device__ float    g_S2buf[3][256];   // tau-grad accumulators (reader-zeroed)
__device__ float    g_Lbuf[3];         // loss accumulators (reader-zeroed)
__device__ float    g_Lp[128];         // epilogue per-block loss partials
__device__ unsigned g_gc[3];           // per-slot head-arrival counters (monotonic)
__device__ unsigned g_barcnt;          // for the 2 real grid barriers

// ---------------- helpers ----------------
static __device__ __forceinline__ unsigned ld_acq(const unsigned* p) {
    unsigned v; asm volatile("ld.acquire.gpu.global.u32 %0,[%1];" : "=r"(v) : "l"(p)); return v;
}
static __device__ __forceinline__ float ldcg(const float* p) {
    float v; asm volatile("ld.global.cg.f32 %0,[%1];" : "=f"(v) : "l"(p)); return v;
}
static __device__ __forceinline__ float4 ldcg4(const float4* p) {
    float4 v;
    asm volatile("ld.global.cg.v4.f32 {%0,%1,%2,%3},[%4];"
                 : "=f"(v.x), "=f"(v.y), "=f"(v.z), "=f"(v.w) : "l"(p));
    return v;
}
static __device__ __forceinline__ void redadd(float* p, float v) {
    asm volatile("red.global.add.f32 [%0],%1;" :: "l"(p), "f"(v) : "memory");
}
static __device__ __forceinline__ float rcpa(float x) {
    float r; asm("rcp.approx.f32 %0,%1;" : "=f"(r) : "f"(x)); return r;
}
static __device__ __forceinline__ u64 fma2_(u64 a, u64 b, u64 c) {
    u64 d; asm("fma.rn.f32x2 %0,%1,%2,%3;" : "=l"(d) : "l"(a), "l"(b), "l"(c)); return d;
}
static __device__ __forceinline__ u64 mul2_(u64 a, u64 b) {
    u64 d; asm("mul.rn.f32x2 %0,%1,%2;" : "=l"(d) : "l"(a), "l"(b)); return d;
}
static __device__ __forceinline__ float sigm(float x) { return 1.0f / (1.0f + __expf(-x)); }

#define WRED(val, dst) do { float _v = (val);                             \
    _v += __shfl_down_sync(0xffffffffu, _v, 16);                          \
    _v += __shfl_down_sync(0xffffffffu, _v, 8);                           \
    _v += __shfl_down_sync(0xffffffffu, _v, 4);                           \
    _v += __shfl_down_sync(0xffffffffu, _v, 2);                           \
    _v += __shfl_down_sync(0xffffffffu, _v, 1);                           \
    if ((tx & 31) == 0) (dst)[tx >> 5] = _v; } while (0)

static __device__ __forceinline__ float sum8(const float* w, int g) {
    float s = 0.f;
    #pragma unroll
    for (int i = 0; i < 8; ++i) s += w[g * 8 + i];
    return s;
}

#define GRIDBAR() do { __syncthreads();                                   \
    if (tx == 0) { __threadfence(); atomicAdd(&g_barcnt, 1u);             \
        while (ld_acq(&g_barcnt) < bartgt) __nanosleep(32); }             \
    bartgt += NB; __syncthreads(); } while (0)

#define QUADACC(t01u, t23u, n01u, n23u, acc, bad) do {                    \
    F2 _t0; _t0.u = (t01u); F2 _t1; _t1.u = (t23u);                       \
    F2 _n0; _n0.u = (n01u); F2 _n1; _n1.u = (n23u);                       \
    float _P01 = _t0.f.x * _t0.f.y;                                       \
    float _P23 = _t1.f.x * _t1.f.y;                                       \
    float _T = _P01 * _P23;                                               \
    float _r = rcpa(_T);                                                  \
    float _m1 = fmaf(_n0.f.y, _t0.f.x, _n0.f.x * _t0.f.y);                \
    float _m3 = fmaf(_n1.f.y, _t1.f.x, _n1.f.x * _t1.f.y);                \
    float _s = fmaf(_m3, _P01, _m1 * _P23);                               \
    bool _ok = (_T != 0.f);                                               \
    acc += _ok ? _s * _r : 0.f;                                           \
    bad |= !_ok; } while (0)

// ---------------- persistent kernel ----------------
__global__ void __launch_bounds__(1024, 1) gflow(
    const float* __restrict__ A, const float* __restrict__ Gl0,
    const float* __restrict__ tau0, float* __restrict__ out)
{
    const int b  = blockIdx.x;
    const int tx = threadIdx.x;
    const int Q  = tx >> 8;
    const int U  = tx & 255;
    const int r0 = b, r1 = b + NB;

    __shared__ u64   GnaP[120], GnbP[120];
    __shared__ float4 DsA4[60], DsB4[60];
    __shared__ float pfA[4 * NM], pfB[4 * NM];
    __shared__ float taus[NN];
    __shared__ float msh[NN], vsh[NN];
    __shared__ float wsum[32], wsum2[32];
    __shared__ float lsh;
    float* GnaF = (float*)GnaP;
    float* GnbF = (float*)GnbP;
    const ulonglong2* At8  = (const ulonglong2*)g_At4;
    const ulonglong2* Ab8  = (const ulonglong2*)g_Ab4;
    const ulonglong2* DsA8 = (const ulonglong2*)DsA4;
    const ulonglong2* DsB8 = (const ulonglong2*)DsB4;
    const ulonglong2* GnaP2 = (const ulonglong2*)GnaP;
    const ulonglong2* GnbP2 = (const ulonglong2*)GnbP;

    unsigned bartgt = (ld_acq(&g_barcnt) / PER_LAUNCH) * PER_LAUNCH + NB;
    // per-slot counter bases: counters are multiples of 1200 at launch start;
    // <120 stray arrivals possible before this read -> floor is exact.
    unsigned gb0 = (ld_acq(&g_gc[0]) / 1200u) * 1200u;
    unsigned gb1 = (ld_acq(&g_gc[1]) / 1200u) * 1200u;
    unsigned gb2 = (ld_acq(&g_gc[2]) / 1200u) * 1200u;

    // ---- init: repack A (both layouts), buffers, params ----
    if (tx < 120) {
        int e = b * 120 + tx, kb = e / NM, j = e % NM;
        g_At4[e] = *(const float4*)(A + j * NN + 16 + 4 * kb);
        float4 v;
        v.x = A[(4 * kb + 0) * NN + 16 + j];
        v.y = A[(4 * kb + 1) * NN + 16 + j];
        v.z = A[(4 * kb + 2) * NN + 16 + j];
        v.w = A[(4 * kb + 3) * NN + 16 + j];
        g_Ab4[e] = v;
    }
    if (b == 0) {
        if (tx < 768) ((float*)g_S2buf)[tx] = 0.f;
        if (tx >= 768 && tx < 771) g_Lbuf[tx - 768] = 0.f;
    }
    float gl = 0.f, mg = 0.f, vg = 0.f;
    if (Q < 2 && U < NM) gl = Gl0[(Q ? r1 : r0) * NM + U];
    if (tx < NN) { taus[tx] = tau0[tx]; msh[tx] = 0.f; vsh[tx] = 0.f; }
    GRIDBAR();  // barrier #1: A repack + buffer init complete

    double b1t = 1.0, b2t = 1.0;
    float bc1p = 1.f, bc2p = 1.f;
    int stop = 0;

    for (int t = 0; t < ITERS; ++t) {
        b1t *= 0.9; b2t *= 0.999;
        const float bc1c = (float)(1.0 / (1.0 - b1t));
        const float bc2c = (float)(1.0 / (1.0 - b2t));
        const int cs = t % 3;
        float sreg = 0.f;

        // ================= HEAD =================
        if (t > 0) {
            const int ps = (t + 2) % 3;   // (t-1)%3
            unsigned gb = (ps == 0) ? gb0 : ((ps == 1) ? gb1 : gb2);
            unsigned tgt = gb + ((unsigned)((t - 1) / 3) + 1u) * 120u;
            if (tx == 0) { while (ld_acq(&g_gc[ps]) < tgt) __nanosleep(32); }
            __syncthreads();   // broadcast acquire to whole block
            float s2v = 0.f;
            if (tx < 256) { s2v = ldcg(&g_S2buf[ps][tx]); g_S2buf[ps][tx] = 0.f; }
            if (t >= 2) {
                const int lsl = (t + 1) % 3;   // (t-2)%3
                if (tx == 0) { lsh = ldcg(&g_Lbuf[lsl]); g_Lbuf[lsl] = 0.f; }
            }
            if (!stop && tx < 256) {   // tau Adam, step t-1
                float g = -(2.f / 61440.f) * s2v;
                float mm = 0.9f * msh[tx] + 0.1f * g;
                float vv = 0.999f * vsh[tx] + 0.001f * g * g;
                msh[tx] = mm; vsh[tx] = vv;
                taus[tx] -= 0.1f * (mm * bc1p) / (sqrtf(vv * bc2p) + 1e-8f);
            }
        }
        if (Q < 2 && U < NM) {
            sreg = sigm(gl);
            (Q ? GnbF : GnaF)[U] = -2.f * sreg;
        }
        __syncthreads();   // syncA: taus + Gn + lsh published
        if (t >= 2 && !stop && lsh < 1e-3f) stop = 1;

        // head posts: S1 (row sums) + S2 contributions from taus(t), G(t)
        if (!stop) {
            float w = 0.f;
            if (Q < 2 && U < NM)
                w = sreg * fmaxf(taus[Q ? r1 : r0] - taus[16 + U] + 0.1f, 0.f);
            WRED(w, wsum2);
            if (tx >= 16 && tx < 256) {
                const int m = tx;
                float e0 = fmaxf(taus[r0] - taus[m] + 0.1f, 0.f);
                float e1 = fmaxf(taus[r1] - taus[m] + 0.1f, 0.f);
                float c = (-0.5f * GnaF[m - 16]) * e0 + (-0.5f * GnbF[m - 16]) * e1;
                redadd(&g_S2buf[cs][m], c);
            }
        }
        __threadfence();
        __syncthreads();   // syncB: wsum2 published + all reds fenced
        if (tx == 0) {
            if (!stop) {
                redadd(&g_S2buf[cs][r0], -sum8(wsum2, 0));
                redadd(&g_S2buf[cs][r1], -sum8(wsum2, 1));
                __threadfence();
            }
            atomicAdd(&g_gc[cs], 1u);   // arrive (unconditional: keeps counts exact)
        }

        // ================= BODY (overlaps other blocks' heads) =================
        if (!stop) {
            // forward: thread (Q, j=U) -> product over k-quarter Q (prefetched)
            if (U < NM) {
                const int j = U;
                const ulonglong2* ap = At8 + (15 * Q) * NM + j;
                ulonglong2 an = ap[0];
                u64 pa0 = ONES2, pa1 = ONES2, pb0 = ONES2, pb1 = ONES2;
                #pragma unroll 5
                for (int c = 0; c < 15; ++c) {
                    ulonglong2 a = an;
                    if (c < 14) an = ap[(c + 1) * NM];
                    ulonglong2 ga = GnaP2[15 * Q + c];
                    ulonglong2 gb = GnbP2[15 * Q + c];
                    pa0 = mul2_(pa0, fma2_(a.x, ga.x, ONES2));
                    pa1 = mul2_(pa1, fma2_(a.y, ga.y, ONES2));
                    pb0 = mul2_(pb0, fma2_(a.x, gb.x, ONES2));
                    pb1 = mul2_(pb1, fma2_(a.y, gb.y, ONES2));
                }
                F2 x0; x0.u = pa0; F2 x1; x1.u = pa1;
                pfA[Q * NM + j] = (x0.f.x * x0.f.y) * (x1.f.x * x1.f.y);
                x0.u = pb0; x1.u = pb1;
                pfB[Q * NM + j] = (x0.f.x * x0.f.y) * (x1.f.x * x1.f.y);
            }
            __syncthreads();

            float v = 0.f;
            int nz = 0;
            if (U < NM) {
                const int j = U;
                if (Q == 0) {
                    float P = (pfA[j] * pfA[NM + j]) * (pfA[2 * NM + j] * pfA[3 * NM + j]);
                    float e = P - ((j == r0) ? -1.f : 1.f);
                    v = e * e;
                    float ds = e * P * (1.f / 480.f);
                    ((float*)DsA4)[j] = ds;
                    nz = (ds != 0.f);
                } else if (Q == 1) {
                    float P = (pfB[j] * pfB[NM + j]) * (pfB[2 * NM + j] * pfB[3 * NM + j]);
                    float e = P - ((j == r1) ? -1.f : 1.f);
                    v = e * e;
                    float ds = e * P * (1.f / 480.f);
                    ((float*)DsB4)[j] = ds;
                    nz = (ds != 0.f);
                } else if (Q == 2) {
                    float d = fmaxf(taus[r0] - taus[16 + j] + 0.1f, 0.f);
                    v = (-0.5f * GnaF[j]) * d * d;
                } else {
                    float d = fmaxf(taus[r1] - taus[16 + j] + 0.1f, 0.f);
                    v = (-0.5f * GnbF[j]) * d * d;
                }
            }
            WRED(v, wsum);
            int anyNZ = __syncthreads_or(nz);
            if (tx == 0) {
                float la = sum8(wsum, 0), lb = sum8(wsum, 1);
                float lo = sum8(wsum, 2) + sum8(wsum, 3);
                redadd(&g_Lbuf[cs], (la + lb) * (1.f / 960.f) + lo * (1.f / 61440.f));
            }

            // backward only if any Ds nonzero (P underflows to 0 in fp32)
            if (anyNZ) {
                if (U < NM) {
                    const int k = U;
                    F2 gp; gp.f.x = GnaF[k]; gp.f.y = GnaF[k];
                    const u64 gna2 = gp.u;
                    gp.f.x = GnbF[k]; gp.f.y = GnbF[k];
                    const u64 gnb2 = gp.u;
                    float accA = 0.f, accB = 0.f;
                    bool bad = false;
                    const ulonglong2* abp = Ab8 + (15 * Q) * NM + k;
                    ulonglong2 an = abp[0];
                    #pragma unroll 5
                    for (int c = 0; c < 15; ++c) {
                        ulonglong2 a = an;
                        if (c < 14) an = abp[(c + 1) * NM];
                        ulonglong2 dA = DsA8[15 * Q + c];
                        ulonglong2 dB = DsB8[15 * Q + c];
                        u64 t01 = fma2_(a.x, gna2, ONES2);
                        u64 t23 = fma2_(a.y, gna2, ONES2);
                        u64 n01 = mul2_(dA.x, a.x);
                        u64 n23 = mul2_(dA.y, a.y);
                        QUADACC(t01, t23, n01, n23, accA, bad);
                        t01 = fma2_(a.x, gnb2, ONES2);
                        t23 = fma2_(a.y, gnb2, ONES2);
                        n01 = mul2_(dB.x, a.x);
                        n23 = mul2_(dB.y, a.y);
                        QUADACC(t01, t23, n01, n23, accB, bad);
                    }
                    if (bad) {   // exact-zero term: safe redo (rare)
                        accA = 0.f; accB = 0.f;
                        const float gna = GnaF[k], gnb = GnbF[k];
                        for (int c = 0; c < 15; ++c) {
                            int jb = 15 * Q + c;
                            float4 a4 = g_Ab4[jb * NM + k];
                            float4 dA = DsA4[jb], dB = DsB4[jb];
                            const float* av = (const float*)&a4;
                            const float* dv = (const float*)&dA;
                            const float* ev = (const float*)&dB;
                            #pragma unroll
                            for (int e2 = 0; e2 < 4; ++e2) {
                                float tA = fmaf(av[e2], gna, 1.f);
                                float tB = fmaf(av[e2], gnb, 1.f);
                                accA += (tA != 0.f) ? __fdividef(dv[e2] * av[e2], tA) : 0.f;
                                accB += (tB != 0.f) ? __fdividef(ev[e2] * av[e2], tB) : 0.f;
                            }
                        }
                    }
                    pfA[Q * NM + k] = accA;
                    pfB[Q * NM + k] = accB;
                }
                __syncthreads();
            }

            // Adam(G), step t
            if (Q < 2 && U < NM) {
                const int k = U;
                float S = 0.f;
                if (anyNZ) {
                    const float* pf = Q ? pfB : pfA;
                    S = (pf[k] + pf[NM + k]) + (pf[2 * NM + k] + pf[3 * NM + k]);
                }
                float s = -0.5f * (Q ? GnbF : GnaF)[k];
                float d = fmaxf(taus[Q ? r1 : r0] - taus[16 + k] + 0.1f, 0.f);
                float grad = (-2.f * S + d * d * (1.f / 61440.f)) * (s * (1.f - s));
                mg = 0.9f * mg + 0.1f * grad;
                vg = 0.999f * vg + 0.001f * grad * grad;
                gl -= 0.1f * (mg * bc1c) / (sqrtf(vg * bc2c) + 1e-8f);
            }
        }
        bc1p = bc1c; bc2p = bc2c;
    }

    // ---- final tau update (Adam step 29): wait for all head(29) posts ----
    {
        unsigned tgt = gb2 + 1200u;   // slot 2 fully used (10 x 120)
        if (tx == 0) { while (ld_acq(&g_gc[2]) < tgt) __nanosleep(32); }
        __syncthreads();
        float s = (tx < 256) ? ldcg(&g_S2buf[2][tx]) : 0.f;
        if (tx < 256) g_S2buf[2][tx] = 0.f;   // leave clean for next launch
        if (!stop && tx < 256) {
            float g = -(2.f / 61440.f) * s;
            float mm = 0.9f * msh[tx] + 0.1f * g;
            float vv = 0.999f * vsh[tx] + 0.001f * g * g;
            taus[tx] -= 0.1f * (mm * bc1p) / (sqrtf(vv * bc2p) + 1e-8f);
        }
        __syncthreads();
    }

    // ---- epilogue: final loss at p_final ----
    if (Q < 2 && U < NM) (Q ? GnbF : GnaF)[U] = -2.f * sigm(gl);
    __syncthreads();
    if (U < NM) {
        const int j = U;
        const ulonglong2* ap = At8 + (15 * Q) * NM + j;
        ulonglong2 an = ap[0];
        u64 pa0 = ONES2, pa1 = ONES2, pb0 = ONES2, pb1 = ONES2;
        #pragma unroll 5
        for (int c = 0; c < 15; ++c) {
            ulonglong2 a = an;
            if (c < 14) an = ap[(c + 1) * NM];
            ulonglong2 ga = GnaP2[15 * Q + c];
            ulonglong2 gb = GnbP2[15 * Q + c];
            pa0 = mul2_(pa0, fma2_(a.x, ga.x, ONES2));
            pa1 = mul2_(pa1, fma2_(a.y, ga.y, ONES2));
            pb0 = mul2_(pb0, fma2_(a.x, gb.x, ONES2));
            pb1 = mul2_(pb1, fma2_(a.y, gb.y, ONES2));
        }
        F2 x0; x0.u = pa0; F2 x1; x1.u = pa1;
        pfA[Q * NM + U] = (x0.f.x * x0.f.y) * (x1.f.x * x1.f.y);
        x0.u = pb0; x1.u = pb1;
        pfB[Q * NM + U] = (x0.f.x * x0.f.y) * (x1.f.x * x1.f.y);
    }
    __syncthreads();
    {
        float v = 0.f;
        if (U < NM) {
            const int j = U;
            if (Q == 0) {
                float P = (pfA[j] * pfA[NM + j]) * (pfA[2 * NM + j] * pfA[3 * NM + j]);
                float e = P - ((j == r0) ? -1.f : 1.f);
                v = e * e;
            } else if (Q == 1) {
                float P = (pfB[j] * pfB[NM + j]) * (pfB[2 * NM + j] * pfB[3 * NM + j]);
                float e = P - ((j == r1) ? -1.f : 1.f);
                v = e * e;
            } else if (Q == 2) {
                float d = fmaxf(taus[r0] - taus[16 + j] + 0.1f, 0.f);
                v = (-0.5f * GnaF[j]) * d * d;
            } else {
                float d = fmaxf(taus[r1] - taus[16 + j] + 0.1f, 0.f);
                v = (-0.5f * GnbF[j]) * d * d;
            }
        }
        WRED(v, wsum);
        __syncthreads();
        if (tx == 0) {
            float la = sum8(wsum, 0), lb = sum8(wsum, 1);
            float lo = sum8(wsum, 2) + sum8(wsum, 3);
            g_Lp[b] = (la + lb) * (1.f / 960.f) + lo * (1.f / 61440.f);
        }
    }
    GRIDBAR();  // barrier #2: all g_Lp + all iteration-29 Lbuf posts quiesced
    if (b == 0) {
        float lv = 0.f;
        if (tx < 30) {
            float4 q = ldcg4(((const float4*)g_Lp) + tx);
            lv = (q.x + q.y) + (q.z + q.w);
        }
        if (tx < 32) {
            lv += __shfl_down_sync(0xffffffffu, lv, 16);
            lv += __shfl_down_sync(0xffffffffu, lv, 8);
            lv += __shfl_down_sync(0xffffffffu, lv, 4);
            lv += __shfl_down_sync(0xffffffffu, lv, 2);
            lv += __shfl_down_sync(0xffffffffu, lv, 1);
            if (tx == 0) out[0] = lv;
        }
        if (tx < 3) g_Lbuf[tx] = 0.f;   // clean unread loss slots for next launch
    }
}

// ---------------- launch ----------------
extern "C" void kernel_launch(void* const* d_in, const int* in_sizes, int n_in,
                              void* d_out, int out_size) {
    const float* A    = (const float*)d_in[0];
    const float* Gl0  = (const float*)d_in[1];
    const float* tau0 = (const float*)d_in[2];
    gflow<<<NB, 1024>>>(A, Gl0, tau0, (float*)d_out);
}